// round 1
// baseline (speedup 1.0000x reference)
#include <cuda_runtime.h>

#define NB 16
#define NPTS 4096
#define NP 512
#define NS 32
#define MROWS (NB*NP*NS)   // 262144 rows

// ---------------- scratch (static __device__ allocations only) ----------------
__device__ float g_newxyz[NB*NP*3];
__device__ float g_h0[9*MROWS];
__device__ float g_h1[64*MROWS];
__device__ float g_h2[64*MROWS];
__device__ float g_h3[128*MROWS];
__device__ float g_a1[64], g_c1[64];
__device__ float g_a2[64], g_c2[64];
__device__ float g_a3[128], g_c3[128];

// ---------------- Stage 1: farthest point sampling ----------------
// One block per batch, 512 threads x 8 points in registers.
// Matches jax scan semantics: centroids[0]=0; dist=min(dist,d); next=argmax (first-index ties).
__global__ void __launch_bounds__(512) fps_kernel(const float* __restrict__ xyz,
                                                  float* __restrict__ out0) {
    const int b = blockIdx.x, tid = threadIdx.x;
    const float* base = xyz + (size_t)b * 3 * NPTS;

    float px[8], py[8], pz[8], dist[8];
#pragma unroll
    for (int j = 0; j < 8; j++) {
        int p = tid * 8 + j;
        px[j] = base[p];
        py[j] = base[NPTS + p];
        pz[j] = base[2 * NPTS + p];
        dist[j] = 1e10f;
    }

    __shared__ float rv[16], rx[16], ry[16], rz[16];
    __shared__ int   ri[16];
    __shared__ float scx, scy, scz;

    float cx = base[0], cy = base[NPTS], cz = base[2 * NPTS];

    for (int it = 0; it < NP; it++) {
        if (tid == 0) {
            g_newxyz[((size_t)b * NP + it) * 3 + 0] = cx;
            g_newxyz[((size_t)b * NP + it) * 3 + 1] = cy;
            g_newxyz[((size_t)b * NP + it) * 3 + 2] = cz;
            out0[((size_t)b * 3 + 0) * NP + it] = cx;
            out0[((size_t)b * 3 + 1) * NP + it] = cy;
            out0[((size_t)b * 3 + 2) * NP + it] = cz;
        }
        float bv = -1.0f, bx = 0.f, by = 0.f, bz = 0.f;
        int bi = 0x7fffffff;
#pragma unroll
        for (int j = 0; j < 8; j++) {
            float dx = __fsub_rn(px[j], cx);
            float dy = __fsub_rn(py[j], cy);
            float dz = __fsub_rn(pz[j], cz);
            float d = __fadd_rn(__fadd_rn(__fmul_rn(dx, dx), __fmul_rn(dy, dy)),
                                __fmul_rn(dz, dz));
            d = fminf(dist[j], d);
            dist[j] = d;
            if (d > bv) { bv = d; bi = tid * 8 + j; bx = px[j]; by = py[j]; bz = pz[j]; }
        }
        // warp argmax (carry coords; ties -> smaller global index)
#pragma unroll
        for (int off = 16; off > 0; off >>= 1) {
            float ov = __shfl_down_sync(0xffffffffu, bv, off);
            int   oi = __shfl_down_sync(0xffffffffu, bi, off);
            float ox = __shfl_down_sync(0xffffffffu, bx, off);
            float oy = __shfl_down_sync(0xffffffffu, by, off);
            float oz = __shfl_down_sync(0xffffffffu, bz, off);
            if (ov > bv || (ov == bv && oi < bi)) { bv = ov; bi = oi; bx = ox; by = oy; bz = oz; }
        }
        if ((tid & 31) == 0) { int w = tid >> 5; rv[w] = bv; ri[w] = bi; rx[w] = bx; ry[w] = by; rz[w] = bz; }
        __syncthreads();
        if (tid < 16) {
            bv = rv[tid]; bi = ri[tid]; bx = rx[tid]; by = ry[tid]; bz = rz[tid];
#pragma unroll
            for (int off = 8; off > 0; off >>= 1) {
                float ov = __shfl_down_sync(0xffffu, bv, off);
                int   oi = __shfl_down_sync(0xffffu, bi, off);
                float ox = __shfl_down_sync(0xffffu, bx, off);
                float oy = __shfl_down_sync(0xffffu, by, off);
                float oz = __shfl_down_sync(0xffffu, bz, off);
                if (ov > bv || (ov == bv && oi < bi)) { bv = ov; bi = oi; bx = ox; by = oy; bz = oz; }
            }
            if (tid == 0) { scx = bx; scy = by; scz = bz; }
        }
        __syncthreads();
        cx = scx; cy = scy; cz = scz;
    }
}

// ---------------- Stage 2: ball query (stable top-32 by distance) + gather ----------------
// One block (256 thr) per query. 32 sequential argmin extractions over shared dist[4096]
// with (value, index) tie-break == jax.lax.top_k(-sq) ordering.
__global__ void __launch_bounds__(256) ball_gather_kernel(const float* __restrict__ xyz,
                                                          const float* __restrict__ points) {
    const int q = blockIdx.x;
    const int b = q >> 9;
    const int tid = threadIdx.x;

    __shared__ float dist[NPTS];
    __shared__ float rv[8];
    __shared__ int   ri[8];
    __shared__ int   sel_i[NS];
    __shared__ float sel_d[NS];

    const float qx = g_newxyz[(size_t)q * 3 + 0];
    const float qy = g_newxyz[(size_t)q * 3 + 1];
    const float qz = g_newxyz[(size_t)q * 3 + 2];
    const float qn = __fadd_rn(__fadd_rn(__fmul_rn(qx, qx), __fmul_rn(qy, qy)),
                               __fmul_rn(qz, qz));
    const float* base = xyz + (size_t)b * 3 * NPTS;

    for (int n = tid; n < NPTS; n += 256) {
        float x = base[n], y = base[NPTS + n], z = base[2 * NPTS + n];
        float pn = __fadd_rn(__fadd_rn(__fmul_rn(x, x), __fmul_rn(y, y)), __fmul_rn(z, z));
        float dt = __fadd_rn(__fadd_rn(__fmul_rn(x, qx), __fmul_rn(y, qy)), __fmul_rn(z, qz));
        dist[n] = __fsub_rn(__fadd_rn(qn, pn), __fmul_rn(2.0f, dt));
    }
    __syncthreads();

    for (int k = 0; k < NS; k++) {
        float bv = 3.0e38f;
        int bi = 0x7fffffff;
        int n = tid;
#pragma unroll
        for (int j = 0; j < NPTS / 256; j++, n += 256) {
            float d = dist[n];
            if (d < bv) { bv = d; bi = n; }   // ascending n per thread -> first occurrence kept
        }
#pragma unroll
        for (int off = 16; off > 0; off >>= 1) {
            float ov = __shfl_down_sync(0xffffffffu, bv, off);
            int   oi = __shfl_down_sync(0xffffffffu, bi, off);
            if (ov < bv || (ov == bv && oi < bi)) { bv = ov; bi = oi; }
        }
        if ((tid & 31) == 0) { rv[tid >> 5] = bv; ri[tid >> 5] = bi; }
        __syncthreads();
        if (tid < 8) {
            bv = rv[tid]; bi = ri[tid];
#pragma unroll
            for (int off = 4; off > 0; off >>= 1) {
                float ov = __shfl_down_sync(0xffu, bv, off);
                int   oi = __shfl_down_sync(0xffu, bi, off);
                if (ov < bv || (ov == bv && oi < bi)) { bv = ov; bi = oi; }
            }
            if (tid == 0) { sel_i[k] = bi; sel_d[k] = bv; dist[bi] = 3.4e38f; }
        }
        __syncthreads();
    }

    // gather + concat into h0 (channel-major [9][MROWS])
    if (tid < NS) {
        int idx = (sel_d[tid] > 0.04f) ? sel_i[0] : sel_i[tid];  // radius^2 = 0.04
        size_t row = (size_t)q * NS + tid;
        float x = base[idx], y = base[NPTS + idx], z = base[2 * NPTS + idx];
        g_h0[0 * (size_t)MROWS + row] = x - qx;
        g_h0[1 * (size_t)MROWS + row] = y - qy;
        g_h0[2 * (size_t)MROWS + row] = z - qz;
        const float* pb = points + (size_t)b * 6 * NPTS;
#pragma unroll
        for (int d = 0; d < 6; d++)
            g_h0[(size_t)(3 + d) * MROWS + row] = pb[(size_t)d * NPTS + idx];
    }
}

// ---------------- Stage 3: pointwise MLP layers ----------------
// Channel-major GEMM: out[o][r] = sum_c W[o][c] * f(in[c][r]) + bias[o]
// f = identity (layer 1) or fused BN+ReLU from previous layer's stats.
template <int IC, bool BN>
__global__ void __launch_bounds__(256) mlp_kernel(const float* __restrict__ in,
                                                  const float* __restrict__ W,
                                                  const float* __restrict__ bias,
                                                  const float* __restrict__ aP,
                                                  const float* __restrict__ cP,
                                                  float* __restrict__ out) {
    __shared__ float Wsh[IC][64];
    __shared__ float bsh[64];
    __shared__ float ash[IC], csh[IC];
    const int tid = threadIdx.x;
    const int ocb = blockIdx.y * 64;

    for (int i = tid; i < IC * 64; i += 256) {
        int c = i >> 6, o = i & 63;
        Wsh[c][o] = W[(size_t)(ocb + o) * IC + c];
    }
    if (tid < 64) bsh[tid] = bias[ocb + tid];
    if (BN) {
        for (int c = tid; c < IC; c += 256) { ash[c] = aP[c]; csh[c] = cP[c]; }
    }
    __syncthreads();

    const size_t r = (size_t)blockIdx.x * 256 + tid;
    float acc[64];
#pragma unroll
    for (int o = 0; o < 64; o++) acc[o] = bsh[o];

#pragma unroll 4
    for (int c = 0; c < IC; c++) {
        float x = in[(size_t)c * MROWS + r];
        if (BN) x = fmaxf(fmaf(ash[c], x, csh[c]), 0.0f);
        const float4* w4 = reinterpret_cast<const float4*>(&Wsh[c][0]);
#pragma unroll
        for (int o4 = 0; o4 < 16; o4++) {
            float4 w = w4[o4];
            acc[o4 * 4 + 0] = fmaf(w.x, x, acc[o4 * 4 + 0]);
            acc[o4 * 4 + 1] = fmaf(w.y, x, acc[o4 * 4 + 1]);
            acc[o4 * 4 + 2] = fmaf(w.z, x, acc[o4 * 4 + 2]);
            acc[o4 * 4 + 3] = fmaf(w.w, x, acc[o4 * 4 + 3]);
        }
    }
#pragma unroll
    for (int o = 0; o < 64; o++) out[(size_t)(ocb + o) * MROWS + r] = acc[o];
}

// ---------------- BN statistics -> folded (a, c) coefficients ----------------
// One block per channel; deterministic fixed-order reduction in double.
__global__ void __launch_bounds__(256) coeff_kernel(const float* __restrict__ h,
                                                    const float* __restrict__ g,
                                                    const float* __restrict__ be,
                                                    float* __restrict__ a,
                                                    float* __restrict__ c) {
    const int ch = blockIdx.x, tid = threadIdx.x;
    const float* p = h + (size_t)ch * MROWS;
    double s = 0.0, s2 = 0.0;
    for (int i = tid; i < MROWS; i += 256) {
        double v = (double)p[i];
        s += v;
        s2 += v * v;
    }
    __shared__ double sh[256], sh2[256];
    sh[tid] = s; sh2[tid] = s2;
    __syncthreads();
    for (int off = 128; off > 0; off >>= 1) {
        if (tid < off) { sh[tid] += sh[tid + off]; sh2[tid] += sh2[tid + off]; }
        __syncthreads();
    }
    if (tid == 0) {
        double mean = sh[0] / (double)MROWS;
        double var = sh2[0] / (double)MROWS - mean * mean;
        double af = (double)g[ch] * rsqrt(var + 1e-5);
        a[ch] = (float)af;
        c[ch] = (float)((double)be[ch] - mean * af);
    }
}

// ---------------- final BN + ReLU + maxpool over NS + transpose ----------------
__global__ void __launch_bounds__(128) pool_kernel(float* __restrict__ out) {
    const int q = blockIdx.x;     // b*512 + s
    const int o = threadIdx.x;    // 0..127
    const float a = g_a3[o], c = g_c3[o];
    const size_t base = (size_t)o * MROWS + (size_t)q * NS;
    float m = -3.4e38f;
#pragma unroll
    for (int j = 0; j < NS; j++) m = fmaxf(m, fmaf(a, g_h3[base + j], c));
    m = fmaxf(m, 0.0f);  // relu(max) == max(relu) (monotone)
    int b = q >> 9, s = q & 511;
    out[(size_t)NB * 3 * NP + ((size_t)b * 128 + o) * NP + s] = m;
}

// ---------------- launch ----------------
extern "C" void kernel_launch(void* const* d_in, const int* in_sizes, int n_in,
                              void* d_out, int out_size) {
    const float* xyz = (const float*)d_in[0];
    const float* pts = (const float*)d_in[1];
    const float* W0 = (const float*)d_in[2];
    const float* b0 = (const float*)d_in[3];
    const float* g0 = (const float*)d_in[4];
    const float* be0 = (const float*)d_in[5];
    const float* W1 = (const float*)d_in[6];
    const float* b1 = (const float*)d_in[7];
    const float* g1 = (const float*)d_in[8];
    const float* be1 = (const float*)d_in[9];
    const float* W2 = (const float*)d_in[10];
    const float* b2 = (const float*)d_in[11];
    const float* g2 = (const float*)d_in[12];
    const float* be2 = (const float*)d_in[13];
    float* out = (float*)d_out;

    void *h0, *h1, *h2, *h3, *a1, *c1, *a2, *c2, *a3, *c3;
    cudaGetSymbolAddress(&h0, g_h0);
    cudaGetSymbolAddress(&h1, g_h1);
    cudaGetSymbolAddress(&h2, g_h2);
    cudaGetSymbolAddress(&h3, g_h3);
    cudaGetSymbolAddress(&a1, g_a1);
    cudaGetSymbolAddress(&c1, g_c1);
    cudaGetSymbolAddress(&a2, g_a2);
    cudaGetSymbolAddress(&c2, g_c2);
    cudaGetSymbolAddress(&a3, g_a3);
    cudaGetSymbolAddress(&c3, g_c3);

    fps_kernel<<<NB, 512>>>(xyz, out);
    ball_gather_kernel<<<NB * NP, 256>>>(xyz, pts);

    mlp_kernel<9, false><<<dim3(MROWS / 256, 1), 256>>>(
        (const float*)h0, W0, b0, nullptr, nullptr, (float*)h1);
    coeff_kernel<<<64, 256>>>((const float*)h1, g0, be0, (float*)a1, (float*)c1);

    mlp_kernel<64, true><<<dim3(MROWS / 256, 1), 256>>>(
        (const float*)h1, W1, b1, (const float*)a1, (const float*)c1, (float*)h2);
    coeff_kernel<<<64, 256>>>((const float*)h2, g1, be1, (float*)a2, (float*)c2);

    mlp_kernel<64, true><<<dim3(MROWS / 256, 2), 256>>>(
        (const float*)h2, W2, b2, (const float*)a2, (const float*)c2, (float*)h3);
    coeff_kernel<<<128, 256>>>((const float*)h3, g2, be2, (float*)a3, (float*)c3);

    pool_kernel<<<NB * NP, 128>>>(out);
}

// round 2
// speedup vs baseline: 1.5137x; 1.5137x over previous
#include <cuda_runtime.h>

#define NB 16
#define NPTS 4096
#define NP 512
#define NS 32
#define MROWS (NB*NP*NS)   // 262144 rows

// ---------------- scratch ----------------
__device__ float g_newxyz[NB*NP*3];
__device__ float g_h0[9*MROWS];
__device__ float g_h1[64*MROWS];
__device__ float g_h2[64*MROWS];
__device__ float g_h3[128*MROWS];
__device__ float2 g_part[128*8];
__device__ float g_a1[64], g_c1[64];
__device__ float g_a2[64], g_c2[64];
__device__ float g_a3[128], g_c3[128];

// =======================================================================
// Stage 1: FPS. One block per batch, 512 thr x 8 pts in regs.
// u64 key = (dist_bits << 32) | (NPTS-1-idx): max => largest dist, ties -> smallest idx.
// Full cloud staged in smem so winner coords are a broadcast read.
// =======================================================================
__global__ void __launch_bounds__(512) fps_kernel(const float* __restrict__ xyz,
                                                  float* __restrict__ out0) {
    extern __shared__ float fsm[];
    float* sx = fsm;
    float* sy = fsm + NPTS;
    float* sz = fsm + 2 * NPTS;
    unsigned long long* rw = (unsigned long long*)(fsm + 3 * NPTS); // [0..15]=warp, [16]=best

    const int b = blockIdx.x, tid = threadIdx.x;
    const float* base = xyz + (size_t)b * 3 * NPTS;

    float px[8], py[8], pz[8], dist[8];
#pragma unroll
    for (int j = 0; j < 8; j++) {
        int p = tid * 8 + j;
        px[j] = base[p];
        py[j] = base[NPTS + p];
        pz[j] = base[2 * NPTS + p];
        sx[p] = px[j]; sy[p] = py[j]; sz[p] = pz[j];
        dist[j] = 1e10f;
    }
    float cx = base[0], cy = base[NPTS], cz = base[2 * NPTS];
    __syncthreads();

    const int wid = tid >> 5, lid = tid & 31;

    for (int it = 0; it < NP; it++) {
        if (tid == 0) {
            g_newxyz[((size_t)b * NP + it) * 3 + 0] = cx;
            g_newxyz[((size_t)b * NP + it) * 3 + 1] = cy;
            g_newxyz[((size_t)b * NP + it) * 3 + 2] = cz;
            out0[((size_t)b * 3 + 0) * NP + it] = cx;
            out0[((size_t)b * 3 + 1) * NP + it] = cy;
            out0[((size_t)b * 3 + 2) * NP + it] = cz;
        }
        // distance update + local argmax
#pragma unroll
        for (int j = 0; j < 8; j++) {
            float dx = __fsub_rn(px[j], cx);
            float dy = __fsub_rn(py[j], cy);
            float dz = __fsub_rn(pz[j], cz);
            float d = __fadd_rn(__fadd_rn(__fmul_rn(dx, dx), __fmul_rn(dy, dy)),
                                __fmul_rn(dz, dz));
            dist[j] = fminf(dist[j], d);
        }
        float bd = dist[0];
#pragma unroll
        for (int j = 1; j < 8; j++) bd = fmaxf(bd, dist[j]);
        int bj = 7;
#pragma unroll
        for (int j = 7; j >= 0; j--) if (dist[j] == bd) bj = j;  // smallest j
        unsigned int bi = (unsigned int)(tid * 8 + bj);
        unsigned long long key =
            ((unsigned long long)__float_as_uint(bd) << 32) |
            (unsigned long long)(NPTS - 1 - bi);
#pragma unroll
        for (int off = 16; off > 0; off >>= 1) {
            unsigned long long o = __shfl_down_sync(0xffffffffu, key, off);
            key = (o > key) ? o : key;
        }
        if (lid == 0) rw[wid] = key;
        __syncthreads();
        if (tid < 16) {
            key = rw[tid];
#pragma unroll
            for (int off = 8; off > 0; off >>= 1) {
                unsigned long long o = __shfl_down_sync(0xffffu, key, off);
                key = (o > key) ? o : key;
            }
            if (tid == 0) rw[16] = key;
        }
        __syncthreads();
        unsigned int widx = (NPTS - 1) - (unsigned int)(rw[16] & 0xffffffffu);
        cx = sx[widx]; cy = sy[widx]; cz = sz[widx];
    }
}

// =======================================================================
// Stage 2: ball query. One block (256 thr) per query, 16 dists/thread in REGS.
// u64 key = (ordered_bits << 32) | n ; min => smallest dist, ties -> smallest n.
// 32 extraction rounds: block-reduce cached local minima, only winner rescans.
// =======================================================================
__device__ __forceinline__ unsigned int f2ord(float f) {
    unsigned int b = __float_as_uint(f);
    return b ^ (0x80000000u | (unsigned int)((int)b >> 31));
}

__global__ void __launch_bounds__(256) ball_gather_kernel(const float* __restrict__ xyz,
                                                          const float* __restrict__ points) {
    const int q = blockIdx.x;
    const int b = q >> 9;
    const int tid = threadIdx.x;
    const int wid = tid >> 5, lid = tid & 31;

    __shared__ unsigned long long rw[8];
    __shared__ unsigned long long sbest;
    __shared__ unsigned long long skey[NS];

    const float qx = g_newxyz[(size_t)q * 3 + 0];
    const float qy = g_newxyz[(size_t)q * 3 + 1];
    const float qz = g_newxyz[(size_t)q * 3 + 2];
    const float qn = __fadd_rn(__fadd_rn(__fmul_rn(qx, qx), __fmul_rn(qy, qy)),
                               __fmul_rn(qz, qz));
    const float* base = xyz + (size_t)b * 3 * NPTS;

    unsigned long long key[16];
#pragma unroll
    for (int j = 0; j < 16; j++) {
        int n = tid + 256 * j;
        float x = base[n], y = base[NPTS + n], z = base[2 * NPTS + n];
        float pn = __fadd_rn(__fadd_rn(__fmul_rn(x, x), __fmul_rn(y, y)), __fmul_rn(z, z));
        float dt = __fadd_rn(__fadd_rn(__fmul_rn(x, qx), __fmul_rn(y, qy)), __fmul_rn(z, qz));
        float d = __fsub_rn(__fadd_rn(qn, pn), __fmul_rn(2.0f, dt));
        key[j] = ((unsigned long long)f2ord(d) << 32) | (unsigned long long)n;
    }
    // local min tree
    unsigned long long loc = key[0];
#pragma unroll
    for (int j = 1; j < 16; j++) loc = (key[j] < loc) ? key[j] : loc;

    for (int k = 0; k < NS; k++) {
        unsigned long long v = loc;
#pragma unroll
        for (int off = 16; off > 0; off >>= 1) {
            unsigned long long o = __shfl_down_sync(0xffffffffu, v, off);
            v = (o < v) ? o : v;
        }
        if (lid == 0) rw[wid] = v;
        __syncthreads();
        if (tid < 8) {
            v = rw[tid];
#pragma unroll
            for (int off = 4; off > 0; off >>= 1) {
                unsigned long long o = __shfl_down_sync(0xffu, v, off);
                v = (o < v) ? o : v;
            }
            if (tid == 0) { sbest = v; skey[k] = v; }
        }
        __syncthreads();
        unsigned int n = (unsigned int)(sbest & 0xffffffffu);
        if ((int)(n & 255u) == tid) {
            key[n >> 8] = ~0ull;
            loc = key[0];
#pragma unroll
            for (int j = 1; j < 16; j++) loc = (key[j] < loc) ? key[j] : loc;
        }
        __syncthreads();
    }

    // gather + concat into h0 (channel-major [9][MROWS])
    if (tid < NS) {
        const unsigned int uth = __float_as_uint(0.04f) ^ 0x80000000u; // ordered(radius^2)
        unsigned long long kk = skey[tid];
        unsigned int u = (unsigned int)(kk >> 32);
        unsigned int n0 = (unsigned int)(skey[0] & 0xffffffffu);
        unsigned int idx = (u > uth) ? n0 : (unsigned int)(kk & 0xffffffffu);
        size_t row = (size_t)q * NS + tid;
        float x = base[idx], y = base[NPTS + idx], z = base[2 * NPTS + idx];
        g_h0[0 * (size_t)MROWS + row] = x - qx;
        g_h0[1 * (size_t)MROWS + row] = y - qy;
        g_h0[2 * (size_t)MROWS + row] = z - qz;
        const float* pb = points + (size_t)b * 6 * NPTS;
#pragma unroll
        for (int d = 0; d < 6; d++)
            g_h0[(size_t)(3 + d) * MROWS + row] = pb[(size_t)d * NPTS + idx];
    }
}

// =======================================================================
// Stage 3: pointwise MLP via packed f32x2 FMA (2 output channels / instr).
// =======================================================================
__device__ __forceinline__ void fma2(unsigned long long& acc, unsigned long long w,
                                     unsigned long long x) {
    asm("fma.rn.f32x2 %0, %1, %2, %0;" : "+l"(acc) : "l"(w), "l"(x));
}

template <int IC, bool BN>
__global__ void __launch_bounds__(256) mlp_kernel(const float* __restrict__ in,
                                                  const float* __restrict__ W,
                                                  const float* __restrict__ bias,
                                                  const float* __restrict__ aP,
                                                  const float* __restrict__ cP,
                                                  float* __restrict__ out) {
    __shared__ __align__(16) float Wsh[IC][64];
    __shared__ float bsh[64];
    __shared__ float ash[IC], csh[IC];
    const int tid = threadIdx.x;
    const int ocb = blockIdx.y * 64;

    for (int i = tid; i < IC * 64; i += 256) {
        int c = i >> 6, o = i & 63;
        Wsh[c][o] = W[(size_t)(ocb + o) * IC + c];
    }
    if (tid < 64) bsh[tid] = bias[ocb + tid];
    if (BN) {
        for (int c = tid; c < IC; c += 256) { ash[c] = aP[c]; csh[c] = cP[c]; }
    }
    __syncthreads();

    const size_t r = (size_t)blockIdx.x * 256 + tid;
    const float* inr = in + r;

    unsigned long long acc[32];
#pragma unroll
    for (int k = 0; k < 32; k++)
        asm("mov.b64 %0, {%1, %2};" : "=l"(acc[k]) : "f"(bsh[2 * k]), "f"(bsh[2 * k + 1]));

#pragma unroll 8
    for (int c = 0; c < IC; c++) {
        float x = inr[(size_t)c * MROWS];
        if (BN) x = fmaxf(fmaf(ash[c], x, csh[c]), 0.0f);
        unsigned long long x2;
        asm("mov.b64 %0, {%1, %1};" : "=l"(x2) : "f"(x));
        const ulonglong2* w4 = reinterpret_cast<const ulonglong2*>(&Wsh[c][0]);
#pragma unroll
        for (int k4 = 0; k4 < 16; k4++) {
            ulonglong2 w = w4[k4];
            fma2(acc[2 * k4 + 0], w.x, x2);
            fma2(acc[2 * k4 + 1], w.y, x2);
        }
    }
    float* outr = out + (size_t)ocb * MROWS + r;
#pragma unroll
    for (int k = 0; k < 32; k++) {
        float lo, hi;
        asm("mov.b64 {%0, %1}, %2;" : "=f"(lo), "=f"(hi) : "l"(acc[k]));
        outr[(size_t)(2 * k) * MROWS] = lo;
        outr[(size_t)(2 * k + 1) * MROWS] = hi;
    }
}

// =======================================================================
// BN stats: partial sums (float, fixed order) over (nch x 8) grid,
// then tiny double combine -> folded (a, c).
// =======================================================================
__global__ void __launch_bounds__(256) coeffp_kernel(const float* __restrict__ h,
                                                     float2* __restrict__ part) {
    const int ch = blockIdx.x, seg = blockIdx.y, tid = threadIdx.x;
    const float4* p = reinterpret_cast<const float4*>(h + (size_t)ch * MROWS + (size_t)seg * 32768);
    float s = 0.f, s2 = 0.f;
    for (int i = tid; i < 8192; i += 256) {
        float4 v = p[i];
        s += ((v.x + v.y) + (v.z + v.w));
        s2 += ((v.x * v.x + v.y * v.y) + (v.z * v.z + v.w * v.w));
    }
    __shared__ float sh[256], sh2[256];
    sh[tid] = s; sh2[tid] = s2;
    __syncthreads();
    for (int off = 128; off > 0; off >>= 1) {
        if (tid < off) { sh[tid] += sh[tid + off]; sh2[tid] += sh2[tid + off]; }
        __syncthreads();
    }
    if (tid == 0) part[ch * 8 + seg] = make_float2(sh[0], sh2[0]);
}

__global__ void comb_kernel(const float2* __restrict__ part,
                            const float* __restrict__ g,
                            const float* __restrict__ be,
                            float* __restrict__ a, float* __restrict__ c, int nch) {
    int ch = threadIdx.x;
    if (ch >= nch) return;
    double s = 0.0, s2 = 0.0;
    for (int i = 0; i < 8; i++) {
        float2 p = part[ch * 8 + i];
        s += (double)p.x; s2 += (double)p.y;
    }
    double mean = s / (double)MROWS;
    double var = s2 / (double)MROWS - mean * mean;
    double af = (double)g[ch] / sqrt(var + 1e-5);
    a[ch] = (float)af;
    c[ch] = (float)((double)be[ch] - mean * af);
}

// ---------------- final BN + ReLU + maxpool over NS + transpose ----------------
__global__ void __launch_bounds__(128) pool_kernel(float* __restrict__ out) {
    const int q = blockIdx.x;
    const int o = threadIdx.x;
    const float a = g_a3[o], c = g_c3[o];
    const float4* p = reinterpret_cast<const float4*>(g_h3 + (size_t)o * MROWS + (size_t)q * NS);
    float m = -3.4e38f;
#pragma unroll
    for (int j = 0; j < 8; j++) {
        float4 v = p[j];
        m = fmaxf(m, fmaf(a, v.x, c));
        m = fmaxf(m, fmaf(a, v.y, c));
        m = fmaxf(m, fmaf(a, v.z, c));
        m = fmaxf(m, fmaf(a, v.w, c));
    }
    m = fmaxf(m, 0.0f);
    int b = q >> 9, s = q & 511;
    out[(size_t)NB * 3 * NP + ((size_t)b * 128 + o) * NP + s] = m;
}

// ---------------- launch ----------------
extern "C" void kernel_launch(void* const* d_in, const int* in_sizes, int n_in,
                              void* d_out, int out_size) {
    const float* xyz = (const float*)d_in[0];
    const float* pts = (const float*)d_in[1];
    const float* W0 = (const float*)d_in[2];
    const float* b0 = (const float*)d_in[3];
    const float* g0 = (const float*)d_in[4];
    const float* be0 = (const float*)d_in[5];
    const float* W1 = (const float*)d_in[6];
    const float* b1 = (const float*)d_in[7];
    const float* g1 = (const float*)d_in[8];
    const float* be1 = (const float*)d_in[9];
    const float* W2 = (const float*)d_in[10];
    const float* b2 = (const float*)d_in[11];
    const float* g2 = (const float*)d_in[12];
    const float* be2 = (const float*)d_in[13];
    float* out = (float*)d_out;

    void *h0, *h1, *h2, *h3, *a1, *c1, *a2, *c2, *a3, *c3, *part;
    cudaGetSymbolAddress(&h0, g_h0);
    cudaGetSymbolAddress(&h1, g_h1);
    cudaGetSymbolAddress(&h2, g_h2);
    cudaGetSymbolAddress(&h3, g_h3);
    cudaGetSymbolAddress(&a1, g_a1);
    cudaGetSymbolAddress(&c1, g_c1);
    cudaGetSymbolAddress(&a2, g_a2);
    cudaGetSymbolAddress(&c2, g_c2);
    cudaGetSymbolAddress(&a3, g_a3);
    cudaGetSymbolAddress(&c3, g_c3);
    cudaGetSymbolAddress(&part, g_part);

    const int fps_smem = 3 * NPTS * 4 + 17 * 8;
    cudaFuncSetAttribute(fps_kernel, cudaFuncAttributeMaxDynamicSharedMemorySize, fps_smem);

    fps_kernel<<<NB, 512, fps_smem>>>(xyz, out);
    ball_gather_kernel<<<NB * NP, 256>>>(xyz, pts);

    mlp_kernel<9, false><<<dim3(MROWS / 256, 1), 256>>>(
        (const float*)h0, W0, b0, nullptr, nullptr, (float*)h1);
    coeffp_kernel<<<dim3(64, 8), 256>>>((const float*)h1, (float2*)part);
    comb_kernel<<<1, 128>>>((const float2*)part, g0, be0, (float*)a1, (float*)c1, 64);

    mlp_kernel<64, true><<<dim3(MROWS / 256, 1), 256>>>(
        (const float*)h1, W1, b1, (const float*)a1, (const float*)c1, (float*)h2);
    coeffp_kernel<<<dim3(64, 8), 256>>>((const float*)h2, (float2*)part);
    comb_kernel<<<1, 128>>>((const float2*)part, g1, be1, (float*)a2, (float*)c2, 64);

    mlp_kernel<64, true><<<dim3(MROWS / 256, 2), 256>>>(
        (const float*)h2, W2, b2, (const float*)a2, (const float*)c2, (float*)h3);
    coeffp_kernel<<<dim3(128, 8), 256>>>((const float*)h3, (float2*)part);
    comb_kernel<<<1, 128>>>((const float2*)part, g2, be2, (float*)a3, (float*)c3, 128);

    pool_kernel<<<NB * NP, 128>>>(out);
}